// round 10
// baseline (speedup 1.0000x reference)
#include <cuda_runtime.h>
#include <cstdint>
#include <math.h>

#define NODE_DIM_   128
#define NUM_IRREPS_ 224
#define SPH_DIM_    480
#define HIDDEN_     576
#define NUM_BASIS_  20
#define N_NODES_    30000
#define N_EDGES_    480000
#define EPB_        16
#define MAXD_       32
#define SORT_BLKS_  148
#define GATE_BYTES_ (2 * EPB_ * 2 * NUM_IRREPS_ * 4)   // 57344

// Scratch (device globals)
__device__ float g_hidden[(size_t)N_NODES_ * NODE_DIM_];
__device__ float g_scalar_out[(size_t)N_NODES_ * HIDDEN_];
__device__ int   g_count[N_NODES_];          // zero at load; re-zeroed each call
__device__ int   g_offs[N_NODES_ + 1];
__device__ int   g_cursor[N_NODES_];
__device__ int   g_perm[N_EDGES_];
__device__ unsigned int g_syncA;             // sort barrier counter (monotonic)

// ---------------------------------------------------------------------------
// Grid-wide spin barrier (monotonic counter; reentrant across graph replays)
// ---------------------------------------------------------------------------
__device__ __forceinline__ void grid_barrier(unsigned int* ctr, int nblk) {
    __syncthreads();
    if (threadIdx.x == 0) {
        __threadfence();
        unsigned int arrive = atomicAdd(ctr, 1u) + 1u;
        unsigned int target = ((arrive - 1u) / (unsigned)nblk + 1u) * (unsigned)nblk;
        unsigned int v;
        do {
            asm volatile("ld.acquire.gpu.u32 %0, [%1];" : "=r"(v) : "l"(ctr));
        } while (v < target);
    }
    __syncthreads();
}

// ---------------------------------------------------------------------------
// Fused counting sort: histogram -> scan (block 0) -> permutation.
// ---------------------------------------------------------------------------
__global__ __launch_bounds__(1024) void sort_kernel(const int* __restrict__ edge_index) {
    const int gsz = gridDim.x * blockDim.x;
    const int gtid = blockIdx.x * blockDim.x + threadIdx.x;

    for (int e = gtid; e < N_EDGES_; e += gsz)
        atomicAdd(&g_count[edge_index[e]], 1);
    grid_barrier(&g_syncA, SORT_BLKS_);

    if (blockIdx.x == 0) {
        __shared__ int s[1024];
        const int C = 30;                    // 1024*30 >= 30000
        const int t = threadIdx.x;
        const int base = t * C;
        int local[C];
        int sum = 0;
        #pragma unroll
        for (int j = 0; j < C; j++) {
            int i = base + j;
            int v = (i < N_NODES_) ? g_count[i] : 0;
            local[j] = sum;
            sum += v;
        }
        s[t] = sum;
        __syncthreads();
        #pragma unroll
        for (int d = 1; d < 1024; d <<= 1) {
            int x = (t >= d) ? s[t - d] : 0;
            __syncthreads();
            s[t] += x;
            __syncthreads();
        }
        int pre = (t > 0) ? s[t - 1] : 0;
        #pragma unroll
        for (int j = 0; j < C; j++) {
            int i = base + j;
            if (i < N_NODES_) {
                int o = pre + local[j];
                g_offs[i] = o;
                g_cursor[i] = o;
                g_count[i] = 0;
            }
        }
        if (t == 1023) g_offs[N_NODES_] = s[1023];
    }
    grid_barrier(&g_syncA, SORT_BLKS_);

    for (int e = gtid; e < N_EDGES_; e += gsz) {
        int d = edge_index[e];
        int p = atomicAdd(&g_cursor[d], 1);
        g_perm[p] = e;
    }
}

// ---------------------------------------------------------------------------
// SGEMM 64x64, 4x4 contiguous microtile (measured 122us on gemm2)
// ---------------------------------------------------------------------------
template <bool DO_SILU>
__global__ __launch_bounds__(256) void sgemm_bias(
    const float* __restrict__ A, const float* __restrict__ B,
    const float* __restrict__ bias, float* __restrict__ C,
    int M, int N, int K) {
    __shared__ __align__(16) float As[16][68];
    __shared__ __align__(16) float Bs[16][64];
    const int bm = blockIdx.y * 64;
    const int bn = blockIdx.x * 64;
    const int tid = threadIdx.x;
    const int tx = tid & 15;
    const int ty = tid >> 4;

    float acc[4][4] = {};

    for (int k0 = 0; k0 < K; k0 += 16) {
        #pragma unroll
        for (int i = 0; i < 4; i++) {
            int idx = tid + 256 * i;
            int m = idx >> 4, k = idx & 15;
            int gm = bm + m;
            As[k][m] = (gm < M) ? A[(size_t)gm * K + k0 + k] : 0.0f;
        }
        #pragma unroll
        for (int i = 0; i < 4; i++) {
            int idx = tid + 256 * i;
            int k = idx >> 6, n = idx & 63;
            Bs[k][n] = B[(size_t)(k0 + k) * N + bn + n];
        }
        __syncthreads();
        #pragma unroll
        for (int k = 0; k < 16; k++) {
            float4 aq = *reinterpret_cast<const float4*>(&As[k][ty * 4]);
            float4 bq = *reinterpret_cast<const float4*>(&Bs[k][tx * 4]);
            float a[4] = {aq.x, aq.y, aq.z, aq.w};
            float b[4] = {bq.x, bq.y, bq.z, bq.w};
            #pragma unroll
            for (int i = 0; i < 4; i++)
                #pragma unroll
                for (int j = 0; j < 4; j++)
                    acc[i][j] = fmaf(a[i], b[j], acc[i][j]);
        }
        __syncthreads();
    }

    float4 bq = *reinterpret_cast<const float4*>(&bias[bn + tx * 4]);
    float bv[4] = {bq.x, bq.y, bq.z, bq.w};
    #pragma unroll
    for (int i = 0; i < 4; i++) {
        int m = bm + ty * 4 + i;
        if (m >= M) continue;
        float4 o;
        float* op = &o.x;
        #pragma unroll
        for (int j = 0; j < 4; j++) {
            float v = acc[i][j] + bv[j];
            if (DO_SILU) v = v / (1.0f + expf(-v));
            op[j] = v;
        }
        *reinterpret_cast<float4*>(&C[(size_t)m * N + bn + tx * 4]) = o;
    }
}

// ---------------------------------------------------------------------------
// Persistent node kernel, EPB=16: 1 barrier / 16 edges, 16-deep gather MLP.
// Gate buffers in dynamic smem (2 x 16 x 448 floats).
// ---------------------------------------------------------------------------
__device__ __forceinline__ int irrep_of(int k) {
    if (k < 128) return k;
    if (k < 320) return 128 + (k - 128) / 3;
    return 192 + (k - 320) / 5;
}

__global__ __launch_bounds__(576, 1) void node_kernel(
    const float* __restrict__ rbf, const float* __restrict__ fcut,
    const float* __restrict__ rsh, const int* __restrict__ edge_index,
    const float* __restrict__ Wrbf, const float* __restrict__ brbf,
    const float* __restrict__ x_scalar, const float* __restrict__ x_sph,
    float* __restrict__ out_scalar, float* __restrict__ out_sph) {
    const float* __restrict__ scalar_out = g_scalar_out;

    extern __shared__ float gate_dyn[];     // [2][EPB_][448]
    __shared__ __align__(16) float rbf_s[MAXD_][24];
    __shared__ int   eid_s[MAXD_];
    __shared__ int   src_s[MAXD_];
    __shared__ float fc_s[MAXD_];

    const int t = threadIdx.x;

    float w[NUM_BASIS_];
    #pragma unroll
    for (int k = 0; k < NUM_BASIS_; k++) w[k] = Wrbf[k * HIDDEN_ + t];
    const float bb = brbf[t];
    const int ir = (t < SPH_DIM_) ? irrep_of(t) : 0;
    const bool is_sph = (t < SPH_DIM_);

    int pp = 0;

    for (int n = blockIdx.x; n < N_NODES_; n += gridDim.x) {
        const int off = g_offs[n];
        const int deg = g_offs[n + 1] - off;

        float acc_sph = 0.0f;
        float acc_sc  = 0.0f;

        for (int c0 = 0; c0 < deg; c0 += MAXD_) {
            const int cnt = min(MAXD_, deg - c0);

            // ---- chunk metadata (pad with edge j=0, fc=0) ----
            if (t < MAXD_) {
                int j = (t < cnt) ? t : 0;
                int eid = __ldg(&g_perm[off + c0 + j]);
                eid_s[t] = eid;
                src_s[t] = __ldg(&edge_index[N_EDGES_ + eid]);
                fc_s[t]  = (t < cnt) ? __ldg(&fcut[eid]) : 0.0f;
            }
            for (int i = t; i < cnt * NUM_BASIS_; i += 576) {
                int e = i / NUM_BASIS_, k = i % NUM_BASIS_;
                int eid = __ldg(&g_perm[off + c0 + e]);     // L1 broadcast
                rbf_s[e][k] = __ldg(&rbf[(size_t)eid * NUM_BASIS_ + k]);
            }
            __syncthreads();

            const int nb = (cnt + EPB_ - 1) / EPB_;   // 1..2
            for (int b = 0; b < nb; b++) {
                const int base = b * EPB_;
                float* gate = gate_dyn + pp * (EPB_ * 2 * NUM_IRREPS_);

                // 16-deep gathers, all streams issued up front
                float s[EPB_];
                #pragma unroll
                for (int e = 0; e < EPB_; e++)
                    s[e] = __ldg(&scalar_out[(size_t)src_s[base + e] * HIDDEN_ + t]);

                float xv[EPB_], rv[EPB_];
                if (is_sph) {
                    #pragma unroll
                    for (int e = 0; e < EPB_; e++) {
                        xv[e] = __ldg(&x_sph[(size_t)src_s[base + e] * SPH_DIM_ + t]);
                        rv[e] = __ldcs(&rsh[(size_t)eid_s[base + e] * SPH_DIM_ + t]);
                    }
                }

                // filter dots (rbf via float4 broadcast LDS)
                float a[EPB_];
                #pragma unroll
                for (int e = 0; e < EPB_; e++) {
                    const float4* rp =
                        reinterpret_cast<const float4*>(&rbf_s[base + e][0]);
                    float4 q0 = rp[0], q1 = rp[1], q2 = rp[2], q3 = rp[3], q4 = rp[4];
                    float v = bb;
                    v = fmaf(q0.x, w[0],  v); v = fmaf(q0.y, w[1],  v);
                    v = fmaf(q0.z, w[2],  v); v = fmaf(q0.w, w[3],  v);
                    v = fmaf(q1.x, w[4],  v); v = fmaf(q1.y, w[5],  v);
                    v = fmaf(q1.z, w[6],  v); v = fmaf(q1.w, w[7],  v);
                    v = fmaf(q2.x, w[8],  v); v = fmaf(q2.y, w[9],  v);
                    v = fmaf(q2.z, w[10], v); v = fmaf(q2.w, w[11], v);
                    v = fmaf(q3.x, w[12], v); v = fmaf(q3.y, w[13], v);
                    v = fmaf(q3.z, w[14], v); v = fmaf(q3.w, w[15], v);
                    v = fmaf(q4.x, w[16], v); v = fmaf(q4.y, w[17], v);
                    v = fmaf(q4.z, w[18], v); v = fmaf(q4.w, w[19], v);
                    a[e] = v;
                }

                #pragma unroll
                for (int e = 0; e < EPB_; e++)
                    s[e] = s[e] * (a[e] * fc_s[base + e]);

                if (t < 2 * NUM_IRREPS_) {
                    #pragma unroll
                    for (int e = 0; e < EPB_; e++)
                        gate[e * 2 * NUM_IRREPS_ + t] = s[e];
                } else {
                    #pragma unroll
                    for (int e = 0; e < EPB_; e++) acc_sc += s[e];
                }
                __syncthreads();   // gates ready; gathers land during wait

                if (is_sph) {
                    #pragma unroll
                    for (int e = 0; e < EPB_; e++) {
                        const float* ge = gate + e * 2 * NUM_IRREPS_;
                        acc_sph = fmaf(xv[e], ge[ir], acc_sph);
                        acc_sph = fmaf(rv[e], ge[NUM_IRREPS_ + ir], acc_sph);
                    }
                }
                pp ^= 1;
            }
        }

        // residual + single write (covers deg==0 too)
        if (is_sph)
            out_sph[(size_t)n * SPH_DIM_ + t] =
                x_sph[(size_t)n * SPH_DIM_ + t] + acc_sph;
        if (t >= 2 * NUM_IRREPS_) {
            int c = t - 2 * NUM_IRREPS_;
            out_scalar[(size_t)n * NODE_DIM_ + c] =
                x_scalar[(size_t)n * NODE_DIM_ + c] + acc_sc;
        }
    }
}

// ---------------------------------------------------------------------------
extern "C" void kernel_launch(void* const* d_in, const int* in_sizes, int n_in,
                              void* d_out, int out_size) {
    const float* x_scalar = (const float*)d_in[0];
    const float* x_sph    = (const float*)d_in[1];
    const float* rbf      = (const float*)d_in[2];
    const float* fcut     = (const float*)d_in[3];
    const float* rsh      = (const float*)d_in[4];
    const int*   eidx     = (const int*)d_in[5];
    const float* W1       = (const float*)d_in[6];
    const float* b1       = (const float*)d_in[7];
    const float* W2       = (const float*)d_in[8];
    const float* b2       = (const float*)d_in[9];
    const float* Wrbf     = (const float*)d_in[10];
    const float* brbf     = (const float*)d_in[11];

    float* out        = (float*)d_out;
    float* out_scalar = out;
    float* out_sph    = out + (size_t)N_NODES_ * NODE_DIM_;

    float* hidden = nullptr;
    float* so     = nullptr;
    cudaGetSymbolAddress((void**)&hidden, g_hidden);
    cudaGetSymbolAddress((void**)&so, g_scalar_out);

    static int smem_set = 0;
    if (!smem_set) {
        cudaFuncSetAttribute(node_kernel,
                             cudaFuncAttributeMaxDynamicSharedMemorySize,
                             GATE_BYTES_);
        smem_set = 1;
    }

    sort_kernel<<<SORT_BLKS_, 1024>>>(eidx);                                 // 0
    {
        dim3 grid(NODE_DIM_ / 64, (N_NODES_ + 63) / 64);
        sgemm_bias<true><<<grid, 256>>>(x_scalar, W1, b1, hidden,
                                        N_NODES_, NODE_DIM_, NODE_DIM_);     // 1
    }
    {
        dim3 grid(HIDDEN_ / 64, (N_NODES_ + 63) / 64);
        sgemm_bias<false><<<grid, 256>>>(hidden, W2, b2, so,
                                         N_NODES_, HIDDEN_, NODE_DIM_);      // 2
    }
    node_kernel<<<148, 576, GATE_BYTES_>>>(rbf, fcut, rsh, eidx, Wrbf, brbf,
                                           x_scalar, x_sph,
                                           out_scalar, out_sph);             // 3
}

// round 11
// speedup vs baseline: 1.0677x; 1.0677x over previous
#include <cuda_runtime.h>
#include <cstdint>
#include <math.h>

#define NODE_DIM_   128
#define NUM_IRREPS_ 224
#define SPH_DIM_    480
#define HIDDEN_     576
#define NUM_BASIS_  20
#define N_NODES_    30000
#define N_EDGES_    480000
#define EPB_        8
#define MAXD_       32
#define SORT_BLKS_  148

// Scratch (device globals)
__device__ float g_hidden[(size_t)N_NODES_ * NODE_DIM_];
__device__ float g_scalar_out[(size_t)N_NODES_ * HIDDEN_];
__device__ int   g_count[N_NODES_];          // zero at load; re-zeroed each call
__device__ int   g_offs[N_NODES_ + 1];
__device__ int   g_cursor[N_NODES_];
__device__ int   g_perm[N_EDGES_];
__device__ int   g_src_sorted[N_EDGES_];
__device__ float g_fc_sorted[N_EDGES_];
__device__ float g_rbf_sorted[(size_t)N_EDGES_ * NUM_BASIS_];   // 38.4 MB
__device__ unsigned int g_syncA;

// ---------------- packed f32x2 helpers ----------------
__device__ __forceinline__ unsigned long long pack2(float lo, float hi) {
    unsigned long long r;
    asm("mov.b64 %0, {%1, %2};" : "=l"(r) : "f"(lo), "f"(hi));
    return r;
}
__device__ __forceinline__ float2 unpack2(unsigned long long v) {
    float2 f;
    asm("mov.b64 {%0, %1}, %2;" : "=f"(f.x), "=f"(f.y) : "l"(v));
    return f;
}
#define FFMA2(acc, r, w) \
    asm("fma.rn.f32x2 %0, %1, %2, %0;" : "+l"(acc) : "l"(r), "l"(w))

// ---------------------------------------------------------------------------
// Grid-wide spin barrier (monotonic counter; reentrant across graph replays)
// ---------------------------------------------------------------------------
__device__ __forceinline__ void grid_barrier(unsigned int* ctr, int nblk) {
    __syncthreads();
    if (threadIdx.x == 0) {
        __threadfence();
        unsigned int arrive = atomicAdd(ctr, 1u) + 1u;
        unsigned int target = ((arrive - 1u) / (unsigned)nblk + 1u) * (unsigned)nblk;
        unsigned int v;
        do {
            asm volatile("ld.acquire.gpu.u32 %0, [%1];" : "=r"(v) : "l"(ctr));
        } while (v < target);
    }
    __syncthreads();
}

// ---------------------------------------------------------------------------
// Fused counting sort + sorted-metadata materialization:
//   A: histogram   B: scan (block 0)   C: permute + src/fc sorted   D: rbf sorted
// ---------------------------------------------------------------------------
__global__ __launch_bounds__(1024) void sort_kernel(
    const int* __restrict__ edge_index, const float* __restrict__ fcut,
    const float* __restrict__ rbf) {
    const int gsz = gridDim.x * blockDim.x;
    const int gtid = blockIdx.x * blockDim.x + threadIdx.x;

    for (int e = gtid; e < N_EDGES_; e += gsz)
        atomicAdd(&g_count[edge_index[e]], 1);
    grid_barrier(&g_syncA, SORT_BLKS_);

    if (blockIdx.x == 0) {
        __shared__ int s[1024];
        const int C = 30;                    // 1024*30 >= 30000
        const int t = threadIdx.x;
        const int base = t * C;
        int local[C];
        int sum = 0;
        #pragma unroll
        for (int j = 0; j < C; j++) {
            int i = base + j;
            int v = (i < N_NODES_) ? g_count[i] : 0;
            local[j] = sum;
            sum += v;
        }
        s[t] = sum;
        __syncthreads();
        #pragma unroll
        for (int d = 1; d < 1024; d <<= 1) {
            int x = (t >= d) ? s[t - d] : 0;
            __syncthreads();
            s[t] += x;
            __syncthreads();
        }
        int pre = (t > 0) ? s[t - 1] : 0;
        #pragma unroll
        for (int j = 0; j < C; j++) {
            int i = base + j;
            if (i < N_NODES_) {
                int o = pre + local[j];
                g_offs[i] = o;
                g_cursor[i] = o;
                g_count[i] = 0;
            }
        }
        if (t == 1023) g_offs[N_NODES_] = s[1023];
    }
    grid_barrier(&g_syncA, SORT_BLKS_);

    // C: permutation + sorted src/fcut
    for (int e = gtid; e < N_EDGES_; e += gsz) {
        int d = edge_index[e];
        int p = atomicAdd(&g_cursor[d], 1);
        g_perm[p] = e;
        g_src_sorted[p] = edge_index[N_EDGES_ + e];
        g_fc_sorted[p] = fcut[e];
    }
    grid_barrier(&g_syncA, SORT_BLKS_);

    // D: rbf rows into sorted order (coalesced writes; 80B-row gathered reads)
    for (long long i = gtid; i < (long long)N_EDGES_ * NUM_BASIS_; i += gsz) {
        int p = (int)(i / NUM_BASIS_);
        int k = (int)(i - (long long)p * NUM_BASIS_);
        g_rbf_sorted[i] = rbf[(size_t)g_perm[p] * NUM_BASIS_ + k];
    }
}

// ---------------------------------------------------------------------------
// SGEMM 64x64, 4x4 contiguous microtile (measured 122us on gemm2)
// ---------------------------------------------------------------------------
template <bool DO_SILU>
__global__ __launch_bounds__(256) void sgemm_bias(
    const float* __restrict__ A, const float* __restrict__ B,
    const float* __restrict__ bias, float* __restrict__ C,
    int M, int N, int K) {
    __shared__ __align__(16) float As[16][68];
    __shared__ __align__(16) float Bs[16][64];
    const int bm = blockIdx.y * 64;
    const int bn = blockIdx.x * 64;
    const int tid = threadIdx.x;
    const int tx = tid & 15;
    const int ty = tid >> 4;

    float acc[4][4] = {};

    for (int k0 = 0; k0 < K; k0 += 16) {
        #pragma unroll
        for (int i = 0; i < 4; i++) {
            int idx = tid + 256 * i;
            int m = idx >> 4, k = idx & 15;
            int gm = bm + m;
            As[k][m] = (gm < M) ? A[(size_t)gm * K + k0 + k] : 0.0f;
        }
        #pragma unroll
        for (int i = 0; i < 4; i++) {
            int idx = tid + 256 * i;
            int k = idx >> 6, n = idx & 63;
            Bs[k][n] = B[(size_t)(k0 + k) * N + bn + n];
        }
        __syncthreads();
        #pragma unroll
        for (int k = 0; k < 16; k++) {
            float4 aq = *reinterpret_cast<const float4*>(&As[k][ty * 4]);
            float4 bq = *reinterpret_cast<const float4*>(&Bs[k][tx * 4]);
            float a[4] = {aq.x, aq.y, aq.z, aq.w};
            float b[4] = {bq.x, bq.y, bq.z, bq.w};
            #pragma unroll
            for (int i = 0; i < 4; i++)
                #pragma unroll
                for (int j = 0; j < 4; j++)
                    acc[i][j] = fmaf(a[i], b[j], acc[i][j]);
        }
        __syncthreads();
    }

    float4 bq = *reinterpret_cast<const float4*>(&bias[bn + tx * 4]);
    float bv[4] = {bq.x, bq.y, bq.z, bq.w};
    #pragma unroll
    for (int i = 0; i < 4; i++) {
        int m = bm + ty * 4 + i;
        if (m >= M) continue;
        float4 o;
        float* op = &o.x;
        #pragma unroll
        for (int j = 0; j < 4; j++) {
            float v = acc[i][j] + bv[j];
            if (DO_SILU) v = v / (1.0f + expf(-v));
            op[j] = v;
        }
        *reinterpret_cast<float4*>(&C[(size_t)m * N + bn + tx * 4]) = o;
    }
}

// ---------------------------------------------------------------------------
// Persistent node kernel, EPB=8, f32x2 filter. All per-edge metadata comes
// from SORTED arrays -> meta phase is pure sequential loads (no dependent
// pointer chains). Thread t owns filter column t.
// ---------------------------------------------------------------------------
__device__ __forceinline__ int irrep_of(int k) {
    if (k < 128) return k;
    if (k < 320) return 128 + (k - 128) / 3;
    return 192 + (k - 320) / 5;
}

__global__ __launch_bounds__(576, 1) void node_kernel(
    const float* __restrict__ rsh,
    const float* __restrict__ Wrbf, const float* __restrict__ brbf,
    const float* __restrict__ x_scalar, const float* __restrict__ x_sph,
    float* __restrict__ out_scalar, float* __restrict__ out_sph) {
    const float* __restrict__ scalar_out = g_scalar_out;

    __shared__ __align__(8) float2 rbf_p[MAXD_ / 2][NUM_BASIS_]; // lanes = edge pair
    __shared__ int   eid_s[MAXD_];
    __shared__ int   src_s[MAXD_];
    __shared__ float fc_s[MAXD_];
    __shared__ float gate_s[2][EPB_][2 * NUM_IRREPS_];

    const int t = threadIdx.x;

    unsigned long long wp[NUM_BASIS_];
    #pragma unroll
    for (int k = 0; k < NUM_BASIS_; k++) {
        float wv = Wrbf[k * HIDDEN_ + t];
        wp[k] = pack2(wv, wv);
    }
    const unsigned long long bbp = pack2(brbf[t], brbf[t]);
    const int ir = (t < SPH_DIM_) ? irrep_of(t) : 0;
    const bool is_sph = (t < SPH_DIM_);

    // clear rbf_p so padded lanes stay finite (fc=0 kills their contribution)
    for (int i = t; i < (MAXD_ / 2) * NUM_BASIS_ * 2; i += 576)
        reinterpret_cast<float*>(rbf_p)[i] = 0.0f;

    int pp = 0;

    for (int n = blockIdx.x; n < N_NODES_; n += gridDim.x) {
        const int off = g_offs[n];
        const int deg = g_offs[n + 1] - off;

        float acc_sph = 0.0f;
        float acc_sc  = 0.0f;

        for (int c0 = 0; c0 < deg; c0 += MAXD_) {
            const int cnt = min(MAXD_, deg - c0);
            const int bp = off + c0;

            // ---- chunk metadata: ALL sequential loads, no chains ----
            if (t < MAXD_) {
                int j = (t < cnt) ? t : cnt - 1;        // pad with last valid
                eid_s[t] = __ldg(&g_perm[bp + j]);
                src_s[t] = __ldg(&g_src_sorted[bp + j]);
                fc_s[t]  = (t < cnt) ? __ldg(&g_fc_sorted[bp + t]) : 0.0f;
            }
            for (int i = t; i < cnt * NUM_BASIS_; i += 576) {
                int e = i / NUM_BASIS_, k = i - e * NUM_BASIS_;
                float v = __ldg(&g_rbf_sorted[(size_t)bp * NUM_BASIS_ + i]);
                reinterpret_cast<float*>(&rbf_p[e >> 1][k])[e & 1] = v;
            }
            __syncthreads();

            const int nb = (cnt + EPB_ - 1) / EPB_;   // 1..4
            for (int b = 0; b < nb; b++) {
                const int base = b * EPB_;

                // gathers first
                float s[EPB_];
                #pragma unroll
                for (int e = 0; e < EPB_; e++)
                    s[e] = __ldg(&scalar_out[(size_t)src_s[base + e] * HIDDEN_ + t]);

                float xv[EPB_], rv[EPB_];
                if (is_sph) {
                    #pragma unroll
                    for (int e = 0; e < EPB_; e++) {
                        xv[e] = __ldg(&x_sph[(size_t)src_s[base + e] * SPH_DIM_ + t]);
                        rv[e] = __ldcs(&rsh[(size_t)eid_s[base + e] * SPH_DIM_ + t]);
                    }
                }

                // filter dots: packed pairs of edges, f32x2 FMA
                float a[EPB_];
                #pragma unroll
                for (int j = 0; j < EPB_ / 2; j++) {
                    unsigned long long acc = bbp;
                    const unsigned long long* rp =
                        reinterpret_cast<const unsigned long long*>(
                            &rbf_p[(base >> 1) + j][0]);
                    #pragma unroll
                    for (int k = 0; k < NUM_BASIS_; k++)
                        FFMA2(acc, rp[k], wp[k]);
                    float2 u = unpack2(acc);
                    a[2 * j]     = u.x;
                    a[2 * j + 1] = u.y;
                }

                #pragma unroll
                for (int e = 0; e < EPB_; e++)
                    s[e] = s[e] * (a[e] * fc_s[base + e]);

                if (t < 2 * NUM_IRREPS_) {
                    #pragma unroll
                    for (int e = 0; e < EPB_; e++) gate_s[pp][e][t] = s[e];
                } else {
                    #pragma unroll
                    for (int e = 0; e < EPB_; e++) acc_sc += s[e];
                }
                __syncthreads();

                if (is_sph) {
                    #pragma unroll
                    for (int e = 0; e < EPB_; e++) {
                        acc_sph = fmaf(xv[e], gate_s[pp][e][ir], acc_sph);
                        acc_sph = fmaf(rv[e], gate_s[pp][e][NUM_IRREPS_ + ir],
                                       acc_sph);
                    }
                }
                pp ^= 1;
            }
        }

        // residual + single write (covers deg==0 too)
        if (is_sph)
            out_sph[(size_t)n * SPH_DIM_ + t] =
                x_sph[(size_t)n * SPH_DIM_ + t] + acc_sph;
        if (t >= 2 * NUM_IRREPS_) {
            int c = t - 2 * NUM_IRREPS_;
            out_scalar[(size_t)n * NODE_DIM_ + c] =
                x_scalar[(size_t)n * NODE_DIM_ + c] + acc_sc;
        }
    }
}

// ---------------------------------------------------------------------------
extern "C" void kernel_launch(void* const* d_in, const int* in_sizes, int n_in,
                              void* d_out, int out_size) {
    const float* x_scalar = (const float*)d_in[0];
    const float* x_sph    = (const float*)d_in[1];
    const float* rbf      = (const float*)d_in[2];
    const float* fcut     = (const float*)d_in[3];
    const float* rsh      = (const float*)d_in[4];
    const int*   eidx     = (const int*)d_in[5];
    const float* W1       = (const float*)d_in[6];
    const float* b1       = (const float*)d_in[7];
    const float* W2       = (const float*)d_in[8];
    const float* b2       = (const float*)d_in[9];
    const float* Wrbf     = (const float*)d_in[10];
    const float* brbf     = (const float*)d_in[11];

    float* out        = (float*)d_out;
    float* out_scalar = out;
    float* out_sph    = out + (size_t)N_NODES_ * NODE_DIM_;

    float* hidden = nullptr;
    float* so     = nullptr;
    cudaGetSymbolAddress((void**)&hidden, g_hidden);
    cudaGetSymbolAddress((void**)&so, g_scalar_out);

    sort_kernel<<<SORT_BLKS_, 1024>>>(eidx, fcut, rbf);                      // 0
    {
        dim3 grid(NODE_DIM_ / 64, (N_NODES_ + 63) / 64);
        sgemm_bias<true><<<grid, 256>>>(x_scalar, W1, b1, hidden,
                                        N_NODES_, NODE_DIM_, NODE_DIM_);     // 1
    }
    {
        dim3 grid(HIDDEN_ / 64, (N_NODES_ + 63) / 64);
        sgemm_bias<false><<<grid, 256>>>(hidden, W2, b2, so,
                                         N_NODES_, HIDDEN_, NODE_DIM_);      // 2
    }
    node_kernel<<<148, 576>>>(rsh, Wrbf, brbf,
                              x_scalar, x_sph, out_scalar, out_sph);         // 3
}